// round 1
// baseline (speedup 1.0000x reference)
#include <cuda_runtime.h>

#define Hh 51
#define Rr 204      // 4*H gate rows
#define RP 208      // rows padded to 16 slots * 13
#define HP 52       // padded hidden (row stride, float4-aligned)
#define IN2 104     // padded layer-2 input ([h1;h2], each padded to 52)
#define Bt 2048
#define Lt 999
#define NB 16       // batch per CTA
#define NCTA 128
#define THREADS 256
#define XCH 64      // time chunk for x/out staging
#define XCHP 65     // padded (odd -> conflict-free)

// shared memory layout (in floats)
#define OFF_WHH1 0
#define OFF_W2   (OFF_WHH1 + RP*HP)          // 10816
#define OFF_WIH1 (OFF_W2   + RP*IN2)         // +21632
#define OFF_B1   (OFF_WIH1 + RP)
#define OFF_B2   (OFF_B1   + RP)
#define OFF_WLIN (OFF_B2   + RP)             // 52 entries, [51] = b_lin
#define OFF_HCAT (OFF_WLIN + HP)             // IN2*NB : [0..51]=h1(+pad0), [52..103]=h2(+pad0)
#define OFF_C1   (OFF_HCAT + IN2*NB)
#define OFF_C2   (OFF_C1   + HP*NB)
#define OFF_G    (OFF_C2   + HP*NB)          // RP*NB activated gates
#define OFF_XCH  (OFF_G    + RP*NB)          // NB*XCHP
#define OFF_OCH  (OFF_XCH  + NB*XCHP)
#define OFF_OP   (OFF_OCH  + NB*XCHP)        // 256 partials
#define SMEM_FLOATS (OFF_OP + THREADS)

__device__ __forceinline__ float sigf(float x) {
    return 1.0f / (1.0f + __expf(-x));
}

__global__ void __launch_bounds__(THREADS, 1)
lstm_kernel(const float* __restrict__ x,
            const float* __restrict__ gWih1, const float* __restrict__ gWhh1,
            const float* __restrict__ gbih1, const float* __restrict__ gbhh1,
            const float* __restrict__ gWih2, const float* __restrict__ gWhh2,
            const float* __restrict__ gbih2, const float* __restrict__ gbhh2,
            const float* __restrict__ gWlin, const float* __restrict__ gblin,
            float* __restrict__ out)
{
    extern __shared__ float sm[];
    float* whh1 = sm + OFF_WHH1;
    float* w2   = sm + OFF_W2;
    float* wih1 = sm + OFF_WIH1;
    float* b1   = sm + OFF_B1;
    float* b2   = sm + OFF_B2;
    float* wlin = sm + OFF_WLIN;
    float* hcat = sm + OFF_HCAT;
    float* c1s  = sm + OFF_C1;
    float* c2s  = sm + OFF_C2;
    float* gsm  = sm + OFF_G;
    float* xch  = sm + OFF_XCH;
    float* och  = sm + OFF_OCH;
    float* opart= sm + OFF_OP;

    const int tid  = threadIdx.x;
    const int lane = tid & 15;        // batch within CTA
    const int slot = tid >> 4;        // 0..15 row-slot / update-group
    const int r0   = slot * 13;
    const int b0   = blockIdx.x * NB;

    // ---- stage weights into smem (once) ----
    for (int i = tid; i < RP*HP; i += THREADS) {
        int r = i / HP, j = i - r*HP;
        whh1[i] = (r < Rr && j < Hh) ? gWhh1[r*Hh + j] : 0.f;
    }
    for (int i = tid; i < RP*IN2; i += THREADS) {
        int r = i / IN2, j = i - r*IN2;
        float v = 0.f;
        if (r < Rr) {
            if (j < Hh)                    v = gWih2[r*Hh + j];
            else if (j >= HP && j < HP+Hh) v = gWhh2[r*Hh + (j - HP)];
        }
        w2[i] = v;
    }
    for (int i = tid; i < RP; i += THREADS) {
        wih1[i] = (i < Rr) ? gWih1[i] : 0.f;
        b1[i]   = (i < Rr) ? (gbih1[i] + gbhh1[i]) : 0.f;
        b2[i]   = (i < Rr) ? (gbih2[i] + gbhh2[i]) : 0.f;
    }
    if (tid < HP) wlin[tid] = (tid < Hh) ? gWlin[tid] : ((tid == Hh) ? gblin[0] : 0.f);
    for (int i = tid; i < IN2*NB; i += THREADS) hcat[i] = 0.f;
    for (int i = tid; i < HP*NB; i += THREADS) { c1s[i] = 0.f; c2s[i] = 0.f; }
    __syncthreads();

    int t0 = 0;
    for (int t = 0; t < Lt; ++t) {
        // ---- chunk boundary: stage x (coalesced) ----
        if ((t & (XCH-1)) == 0) {
            t0 = t;
            int w = Lt - t0; if (w > XCH) w = XCH;
            for (int i = tid; i < NB*XCH; i += THREADS) {
                int row = i >> 6, col = i & 63;
                xch[row*XCHP + col] = (col < w) ? x[(b0+row)*Lt + t0 + col] : 0.f;
            }
            __syncthreads();
        }
        const int tloc = t - t0;
        const float xv = xch[lane*XCHP + tloc];

        // ---- Stage A: layer-1 gates = Wih1*x + Whh1@h1 + bias ----
        {
            float acc[13];
            #pragma unroll
            for (int rr = 0; rr < 13; rr++)
                acc[rr] = fmaf(wih1[r0+rr], xv, b1[r0+rr]);
            #pragma unroll 4
            for (int jc = 0; jc < 13; jc++) {
                const int j = jc * 4;
                const float h0 = hcat[(j+0)*NB + lane];
                const float h1v = hcat[(j+1)*NB + lane];
                const float h2v = hcat[(j+2)*NB + lane];
                const float h3v = hcat[(j+3)*NB + lane];
                #pragma unroll
                for (int rr = 0; rr < 13; rr++) {
                    const float4 wv = *(const float4*)&whh1[(r0+rr)*HP + j];
                    acc[rr] = fmaf(wv.x, h0,  acc[rr]);
                    acc[rr] = fmaf(wv.y, h1v, acc[rr]);
                    acc[rr] = fmaf(wv.z, h2v, acc[rr]);
                    acc[rr] = fmaf(wv.w, h3v, acc[rr]);
                }
            }
            #pragma unroll
            for (int rr = 0; rr < 13; rr++) {
                const int r = r0 + rr;
                float v = acc[rr];
                v = (r >= 102 && r < 153) ? tanhf(v) : sigf(v);  // g-gate tanh, others sigmoid
                gsm[r*NB + lane] = v;
            }
        }
        __syncthreads();

        // ---- Stage B: layer-1 cell/hidden update ----
        {
            #pragma unroll
            for (int q = 0; q < 3; q++) {
                const int u = slot + q*16;
                const float ai = gsm[u*NB + lane];
                const float af = gsm[(51+u)*NB + lane];
                const float ag = gsm[(102+u)*NB + lane];
                const float ao = gsm[(153+u)*NB + lane];
                const float c  = c1s[u*NB + lane];
                const float cn = fmaf(af, c, ai*ag);
                c1s[u*NB + lane]  = cn;
                hcat[u*NB + lane] = ao * tanhf(cn);
            }
            if (slot < 3) {
                const int u = 48 + slot;
                const float ai = gsm[u*NB + lane];
                const float af = gsm[(51+u)*NB + lane];
                const float ag = gsm[(102+u)*NB + lane];
                const float ao = gsm[(153+u)*NB + lane];
                const float c  = c1s[u*NB + lane];
                const float cn = fmaf(af, c, ai*ag);
                c1s[u*NB + lane]  = cn;
                hcat[u*NB + lane] = ao * tanhf(cn);
            }
        }
        __syncthreads();

        // ---- Stage C: layer-2 gates = [Wih2|Whh2] @ [h1;h2] + bias ----
        {
            float acc[13];
            #pragma unroll
            for (int rr = 0; rr < 13; rr++) acc[rr] = b2[r0+rr];
            #pragma unroll 4
            for (int jc = 0; jc < 26; jc++) {
                const int j = jc * 4;
                const float h0 = hcat[(j+0)*NB + lane];
                const float h1v = hcat[(j+1)*NB + lane];
                const float h2v = hcat[(j+2)*NB + lane];
                const float h3v = hcat[(j+3)*NB + lane];
                #pragma unroll
                for (int rr = 0; rr < 13; rr++) {
                    const float4 wv = *(const float4*)&w2[(r0+rr)*IN2 + j];
                    acc[rr] = fmaf(wv.x, h0,  acc[rr]);
                    acc[rr] = fmaf(wv.y, h1v, acc[rr]);
                    acc[rr] = fmaf(wv.z, h2v, acc[rr]);
                    acc[rr] = fmaf(wv.w, h3v, acc[rr]);
                }
            }
            #pragma unroll
            for (int rr = 0; rr < 13; rr++) {
                const int r = r0 + rr;
                float v = acc[rr];
                v = (r >= 102 && r < 153) ? tanhf(v) : sigf(v);
                gsm[r*NB + lane] = v;
            }
        }
        __syncthreads();

        // ---- Stage D: layer-2 update + output partials ----
        {
            float op = 0.f;
            #pragma unroll
            for (int q = 0; q < 3; q++) {
                const int u = slot + q*16;
                const float ai = gsm[u*NB + lane];
                const float af = gsm[(51+u)*NB + lane];
                const float ag = gsm[(102+u)*NB + lane];
                const float ao = gsm[(153+u)*NB + lane];
                const float c  = c2s[u*NB + lane];
                const float cn = fmaf(af, c, ai*ag);
                const float hn = ao * tanhf(cn);
                c2s[u*NB + lane] = cn;
                hcat[(HP+u)*NB + lane] = hn;
                op = fmaf(hn, wlin[u], op);
            }
            if (slot < 3) {
                const int u = 48 + slot;
                const float ai = gsm[u*NB + lane];
                const float af = gsm[(51+u)*NB + lane];
                const float ag = gsm[(102+u)*NB + lane];
                const float ao = gsm[(153+u)*NB + lane];
                const float c  = c2s[u*NB + lane];
                const float cn = fmaf(af, c, ai*ag);
                const float hn = ao * tanhf(cn);
                c2s[u*NB + lane] = cn;
                hcat[(HP+u)*NB + lane] = hn;
                op = fmaf(hn, wlin[u], op);
            }
            opart[tid] = op;
        }
        __syncthreads();

        // ---- Stage E: reduce output, buffer in smem ----
        if (tid < NB) {
            float s = opart[tid];
            #pragma unroll
            for (int q = 1; q < 16; q++) s += opart[q*16 + tid];
            och[tid*XCHP + tloc] = s + wlin[Hh];   // + b_lin
        }

        // ---- flush output chunk (coalesced) ----
        if (tloc == XCH-1 || t == Lt-1) {
            __syncthreads();
            const int w = tloc + 1;
            for (int i = tid; i < NB*w; i += THREADS) {
                const int row = i / w, col = i - row*w;
                out[(b0+row)*Lt + t0 + col] = och[row*XCHP + col];
            }
        }
    }
}

extern "C" void kernel_launch(void* const* d_in, const int* in_sizes, int n_in,
                              void* d_out, int out_size)
{
    const float* x     = (const float*)d_in[0];
    const float* wih1  = (const float*)d_in[1];
    const float* whh1  = (const float*)d_in[2];
    const float* bih1  = (const float*)d_in[3];
    const float* bhh1  = (const float*)d_in[4];
    const float* wih2  = (const float*)d_in[5];
    const float* whh2  = (const float*)d_in[6];
    const float* bih2  = (const float*)d_in[7];
    const float* bhh2  = (const float*)d_in[8];
    const float* wlin  = (const float*)d_in[9];
    const float* blin  = (const float*)d_in[10];
    float* out = (float*)d_out;

    const size_t smem = (size_t)SMEM_FLOATS * sizeof(float);
    cudaFuncSetAttribute(lstm_kernel, cudaFuncAttributeMaxDynamicSharedMemorySize, (int)smem);
    lstm_kernel<<<NCTA, THREADS, smem>>>(x, wih1, whh1, bih1, bhh1,
                                         wih2, whh2, bih2, bhh2,
                                         wlin, blin, out);
}

// round 2
// speedup vs baseline: 1.0016x; 1.0016x over previous
#include <cuda_runtime.h>

#define Hh 51
#define Rr 204      // 4*H gate rows
#define RP 224      // rows padded: 32 slots * 7 rows
#define RPT 7       // rows per thread (slot)
#define HP 52       // layer-1 K (padded hidden), row stride of whh1
#define IN2 104     // layer-2 K ([h1;h2])
#define HS 106      // per-lane h row stride (conflict-free, 8B-aligned)
#define Lt 999
#define NB 16       // batch per CTA
#define NCTA 128
#define THREADS 512
#define NSLOT 32
#define XCH 64      // time chunk for x/out staging
#define XCHP 65

// shared memory layout (floats)
#define OFF_WHH1 0
#define OFF_W2   (OFF_WHH1 + RP*HP)          // 11648
#define OFF_WIH1 (OFF_W2   + RP*IN2)         // 34944
#define OFF_B1   (OFF_WIH1 + RP)
#define OFF_B2   (OFF_B1   + RP)
#define OFF_WLIN (OFF_B2   + RP)             // 52 entries, [51] = b_lin
#define OFF_HROW (OFF_WLIN + HP)             // NB*HS: per-lane [h1(52) | h2(52)] row-major
#define OFF_C1   (OFF_HROW + NB*HS)          // 52*NB
#define OFF_C2   (OFF_C1   + HP*NB)
#define OFF_G    (OFF_C2   + HP*NB)          // RP*NB activated gates
#define OFF_XCH  (OFF_G    + RP*NB)
#define OFF_OCH  (OFF_XCH  + NB*XCHP)
#define OFF_OP   (OFF_OCH  + NB*XCHP)        // 512 partials
#define SMEM_FLOATS (OFF_OP + THREADS)

typedef unsigned long long ull;

__device__ __forceinline__ ull pack2(float lo, float hi) {
    ull d; asm("mov.b64 %0, {%1, %2};" : "=l"(d) : "f"(lo), "f"(hi)); return d;
}
__device__ __forceinline__ void unpack2(ull v, float& lo, float& hi) {
    asm("mov.b64 {%0, %1}, %2;" : "=f"(lo), "=f"(hi) : "l"(v));
}
__device__ __forceinline__ void fma2(ull& d, ull a, ull b) {
    asm("fma.rn.f32x2 %0, %1, %2, %0;" : "+l"(d) : "l"(a), "l"(b));
}
__device__ __forceinline__ float sigf(float x) {
    return 1.0f / (1.0f + __expf(-x));
}
__device__ __forceinline__ float ftanh(float x) {
    // 1 - 2/(exp(2x)+1); exact at +-inf saturation, ~1e-7 rel err
    return 1.0f - 2.0f / (__expf(2.0f * x) + 1.0f);
}

__global__ void __launch_bounds__(THREADS, 1)
lstm_kernel(const float* __restrict__ x,
            const float* __restrict__ gWih1, const float* __restrict__ gWhh1,
            const float* __restrict__ gbih1, const float* __restrict__ gbhh1,
            const float* __restrict__ gWih2, const float* __restrict__ gWhh2,
            const float* __restrict__ gbih2, const float* __restrict__ gbhh2,
            const float* __restrict__ gWlin, const float* __restrict__ gblin,
            float* __restrict__ out)
{
    extern __shared__ float sm[];
    float* whh1 = sm + OFF_WHH1;
    float* w2   = sm + OFF_W2;
    float* wih1 = sm + OFF_WIH1;
    float* b1   = sm + OFF_B1;
    float* b2   = sm + OFF_B2;
    float* wlin = sm + OFF_WLIN;
    float* hrow = sm + OFF_HROW;
    float* c1s  = sm + OFF_C1;
    float* c2s  = sm + OFF_C2;
    float* gsm  = sm + OFF_G;
    float* xch  = sm + OFF_XCH;
    float* och  = sm + OFF_OCH;
    float* opart= sm + OFF_OP;

    const int tid  = threadIdx.x;
    const int lane = tid & 15;        // batch within CTA
    const int slot = tid >> 4;        // 0..31 row-slot
    const int r0   = slot * RPT;
    const int b0   = blockIdx.x * NB;

    // ---- stage weights into smem (once) ----
    for (int i = tid; i < RP*HP; i += THREADS) {
        int r = i / HP, j = i - r*HP;
        whh1[i] = (r < Rr && j < Hh) ? gWhh1[r*Hh + j] : 0.f;
    }
    for (int i = tid; i < RP*IN2; i += THREADS) {
        int r = i / IN2, j = i - r*IN2;
        float v = 0.f;
        if (r < Rr) {
            if (j < Hh)                    v = gWih2[r*Hh + j];
            else if (j >= HP && j < HP+Hh) v = gWhh2[r*Hh + (j - HP)];
        }
        w2[i] = v;
    }
    for (int i = tid; i < RP; i += THREADS) {
        wih1[i] = (i < Rr) ? gWih1[i] : 0.f;
        b1[i]   = (i < Rr) ? (gbih1[i] + gbhh1[i]) : 0.f;
        b2[i]   = (i < Rr) ? (gbih2[i] + gbhh2[i]) : 0.f;
    }
    if (tid < HP) wlin[tid] = (tid < Hh) ? gWlin[tid] : ((tid == Hh) ? gblin[0] : 0.f);
    for (int i = tid; i < NB*HS; i += THREADS) hrow[i] = 0.f;
    for (int i = tid; i < HP*NB; i += THREADS) { c1s[i] = 0.f; c2s[i] = 0.f; }
    __syncthreads();

    const float* hme = hrow + lane * HS;   // this lane's h row ([h1|h2])

    int t0 = 0;
    for (int t = 0; t < Lt; ++t) {
        // ---- chunk boundary: stage x (coalesced) ----
        if ((t & (XCH-1)) == 0) {
            t0 = t;
            int w = Lt - t0; if (w > XCH) w = XCH;
            for (int i = tid; i < NB*XCH; i += THREADS) {
                int row = i >> 6, col = i & 63;
                xch[row*XCHP + col] = (col < w) ? x[(b0+row)*Lt + t0 + col] : 0.f;
            }
            __syncthreads();
        }
        const int tloc = t - t0;
        const float xv = xch[lane*XCHP + tloc];

        // ---- Stage A: layer-1 gates = Wih1*x + Whh1@h1 + bias ----
        {
            ull acc[RPT];
            #pragma unroll
            for (int rr = 0; rr < RPT; rr++)
                acc[rr] = pack2(fmaf(wih1[r0+rr], xv, b1[r0+rr]), 0.f);
            #pragma unroll
            for (int jg = 0; jg < 13; jg++) {
                const int j = jg * 4;
                const ull ha = *(const ull*)(hme + j);
                const ull hb = *(const ull*)(hme + j + 2);
                #pragma unroll
                for (int rr = 0; rr < RPT; rr++) {
                    const ulonglong2 wv = *(const ulonglong2*)(whh1 + (r0+rr)*HP + j);
                    fma2(acc[rr], wv.x, ha);
                    fma2(acc[rr], wv.y, hb);
                }
            }
            #pragma unroll
            for (int rr = 0; rr < RPT; rr++) {
                const int r = r0 + rr;
                float lo, hi; unpack2(acc[rr], lo, hi);
                float v = lo + hi;
                v = (r >= 102 && r < 153) ? ftanh(v) : sigf(v);
                gsm[r*NB + lane] = v;
            }
        }
        __syncthreads();

        // ---- Stage B: layer-1 cell/hidden update (u = slot, slot+32) ----
        {
            #pragma unroll
            for (int q = 0; q < 2; q++) {
                const int u = slot + q*NSLOT;
                if (u < Hh) {
                    const float ai = gsm[u*NB + lane];
                    const float af = gsm[(51+u)*NB + lane];
                    const float ag = gsm[(102+u)*NB + lane];
                    const float ao = gsm[(153+u)*NB + lane];
                    const float c  = c1s[u*NB + lane];
                    const float cn = fmaf(af, c, ai*ag);
                    c1s[u*NB + lane] = cn;
                    hrow[lane*HS + u] = ao * ftanh(cn);
                }
            }
        }
        __syncthreads();

        // ---- Stage C: layer-2 gates = [Wih2|Whh2] @ [h1;h2] + bias ----
        {
            ull acc[RPT];
            #pragma unroll
            for (int rr = 0; rr < RPT; rr++)
                acc[rr] = pack2(b2[r0+rr], 0.f);
            #pragma unroll
            for (int jg = 0; jg < 26; jg++) {
                const int j = jg * 4;
                const ull ha = *(const ull*)(hme + j);
                const ull hb = *(const ull*)(hme + j + 2);
                #pragma unroll
                for (int rr = 0; rr < RPT; rr++) {
                    const ulonglong2 wv = *(const ulonglong2*)(w2 + (r0+rr)*IN2 + j);
                    fma2(acc[rr], wv.x, ha);
                    fma2(acc[rr], wv.y, hb);
                }
            }
            #pragma unroll
            for (int rr = 0; rr < RPT; rr++) {
                const int r = r0 + rr;
                float lo, hi; unpack2(acc[rr], lo, hi);
                float v = lo + hi;
                v = (r >= 102 && r < 153) ? ftanh(v) : sigf(v);
                gsm[r*NB + lane] = v;
            }
        }
        __syncthreads();

        // ---- Stage D: layer-2 update + output partials ----
        {
            float op = 0.f;
            #pragma unroll
            for (int q = 0; q < 2; q++) {
                const int u = slot + q*NSLOT;
                if (u < Hh) {
                    const float ai = gsm[u*NB + lane];
                    const float af = gsm[(51+u)*NB + lane];
                    const float ag = gsm[(102+u)*NB + lane];
                    const float ao = gsm[(153+u)*NB + lane];
                    const float c  = c2s[u*NB + lane];
                    const float cn = fmaf(af, c, ai*ag);
                    const float hn = ao * ftanh(cn);
                    c2s[u*NB + lane] = cn;
                    hrow[lane*HS + HP + u] = hn;
                    op = fmaf(hn, wlin[u], op);
                }
            }
            opart[tid] = op;
        }
        __syncthreads();

        // ---- Stage E: reduce output, buffer in smem ----
        if (tid < NB) {
            float s = opart[tid];
            #pragma unroll
            for (int q = 1; q < NSLOT; q++) s += opart[q*NB + tid];
            och[tid*XCHP + tloc] = s + wlin[Hh];   // + b_lin
        }

        // ---- flush output chunk (coalesced) ----
        if (tloc == XCH-1 || t == Lt-1) {
            __syncthreads();
            const int w = tloc + 1;
            for (int i = tid; i < NB*w; i += THREADS) {
                const int row = i / w, col = i - row*w;
                out[(b0+row)*Lt + t0 + col] = och[row*XCHP + col];
            }
        }
    }
}

extern "C" void kernel_launch(void* const* d_in, const int* in_sizes, int n_in,
                              void* d_out, int out_size)
{
    const float* x     = (const float*)d_in[0];
    const float* wih1  = (const float*)d_in[1];
    const float* whh1  = (const float*)d_in[2];
    const float* bih1  = (const float*)d_in[3];
    const float* bhh1  = (const float*)d_in[4];
    const float* wih2  = (const float*)d_in[5];
    const float* whh2  = (const float*)d_in[6];
    const float* bih2  = (const float*)d_in[7];
    const float* bhh2  = (const float*)d_in[8];
    const float* wlin  = (const float*)d_in[9];
    const float* blin  = (const float*)d_in[10];
    float* out = (float*)d_out;

    const size_t smem = (size_t)SMEM_FLOATS * sizeof(float);
    cudaFuncSetAttribute(lstm_kernel, cudaFuncAttributeMaxDynamicSharedMemorySize, (int)smem);
    lstm_kernel<<<NCTA, THREADS, smem>>>(x, wih1, whh1, bih1, bhh1,
                                         wih2, whh2, bih2, bhh2,
                                         wlin, blin, out);
}